// round 1
// baseline (speedup 1.0000x reference)
#include <cuda_runtime.h>
#include <math.h>

// ---------------- problem constants ----------------
#define B_   4
#define S_   1024
#define D_   1024
#define T_   4096          // B*S tokens
#define H_   16
#define G_   8
#define HD_  64
#define E_   8
#define ED_  2048
#define GH_  512
#define NP_  8192          // T * TOPK pairs

// ---------------- static scratch (allowed: __device__ globals) ----------------
__device__ float g_h  [T_ * D_];                 // ln1 out
__device__ float g_q  [T_ * G_ * HD_];           // [T, 512]
__device__ float g_k  [T_ * D_];
__device__ float g_v  [T_ * D_];
__device__ float g_sc [(size_t)B_ * H_ * S_ * S_];   // 256 MB scores
__device__ float g_ao [T_ * D_];
__device__ float g_x1 [T_ * D_];                 // x + attn
__device__ float g_h2 [T_ * D_];                 // ln2 out
__device__ float g_gh [T_ * GH_];                // gate hidden
__device__ int   g_topi[T_ * 2];
__device__ float g_topw[T_ * 2];
__device__ int   g_cnt[E_];
__device__ int   g_off[E_];
__device__ int   g_cur[E_];
__device__ int   g_pairs[NP_];                   // token id per pair slot
__device__ int   g_pos  [T_ * 2];                // pair slot per (token,k)
__device__ float g_hid [(size_t)NP_ * ED_];      // 64 MB
__device__ float g_eout[(size_t)NP_ * D_];       // 32 MB

// ---------------- buffer tag selectors (avoid cudaGetSymbolAddress) ----------
__device__ __forceinline__ const float* sel_in(int tag) {
    switch (tag) { case 0: return g_h; case 1: return g_ao; default: return g_h2; }
}
__device__ __forceinline__ float* sel_out(int tag) {
    switch (tag) {
        case 0: return g_q; case 1: return g_k; case 2: return g_v;
        case 3: return g_x1; default: return g_gh;
    }
}

// ---------------- misc small kernels ----------------
__global__ void zero_kernel() {
    if (threadIdx.x < E_) { g_cnt[threadIdx.x] = 0; g_cur[threadIdx.x] = 0; }
}

// LayerNorm: one block (256 thr) per row of 1024. in_tag: 0 = x (param), 1 = g_x1.
// out_tag: 0 = g_h, 1 = g_h2.
__global__ void __launch_bounds__(256) ln_kernel(const float* __restrict__ xin, int in_tag,
                                                 const float* __restrict__ gam,
                                                 const float* __restrict__ bet,
                                                 int out_tag)
{
    const float* in  = (in_tag == 0) ? xin : g_x1;
    float*       out = (out_tag == 0) ? g_h : g_h2;
    int t = blockIdx.x, tid = threadIdx.x;
    const float* row = in + (size_t)t * D_;
    int i = tid * 4;
    float4 v = *(const float4*)(row + i);
    __shared__ float red[256];
    red[tid] = v.x + v.y + v.z + v.w;
    __syncthreads();
    for (int o = 128; o; o >>= 1) { if (tid < o) red[tid] += red[tid + o]; __syncthreads(); }
    float mu = red[0] * (1.0f / D_);
    __syncthreads();
    float dx = v.x - mu, dy = v.y - mu, dz = v.z - mu, dw = v.w - mu;
    red[tid] = dx*dx + dy*dy + dz*dz + dw*dw;
    __syncthreads();
    for (int o = 128; o; o >>= 1) { if (tid < o) red[tid] += red[tid + o]; __syncthreads(); }
    float rstd = rsqrtf(red[0] * (1.0f / D_) + 1e-5f);
    float4 go = *(const float4*)(gam + i);
    float4 bo = *(const float4*)(bet + i);
    float4 o4;
    o4.x = dx * rstd * go.x + bo.x;
    o4.y = dy * rstd * go.y + bo.y;
    o4.z = dz * rstd * go.z + bo.z;
    o4.w = dw * rstd * go.w + bo.w;
    *(float4*)(out + (size_t)t * D_ + i) = o4;
}

// ---------------- generic SGEMM: C[T_,N] = A[T_,K] @ W[K,N] + bias (+resid)(+relu)
// 128x128 tile, BK=16, 256 threads, 8x8 micro-tile.
__global__ void __launch_bounds__(256) sgemm_kernel(const float* __restrict__ W,
                                                    const float* __restrict__ bias,
                                                    const float* __restrict__ resid,
                                                    int N, int K, int act,
                                                    int atag, int ctag)
{
    const float* A = sel_in(atag);
    float*       C = sel_out(ctag);
    __shared__ float As[16][128];
    __shared__ float Bs[16][128];
    int tid = threadIdx.x;
    int n0 = blockIdx.x * 128;
    int m0 = blockIdx.y * 128;
    int tx = tid & 15, ty = tid >> 4;
    int am = tid >> 1, ak = (tid & 1) * 8;
    int bk = tid >> 4, bn = (tid & 15) * 8;
    float acc[8][8] = {};
    for (int k0 = 0; k0 < K; k0 += 16) {
        const float* ap = A + (size_t)(m0 + am) * K + k0 + ak;
        float4 a0 = *(const float4*)ap;
        float4 a1 = *(const float4*)(ap + 4);
        As[ak + 0][am] = a0.x; As[ak + 1][am] = a0.y; As[ak + 2][am] = a0.z; As[ak + 3][am] = a0.w;
        As[ak + 4][am] = a1.x; As[ak + 5][am] = a1.y; As[ak + 6][am] = a1.z; As[ak + 7][am] = a1.w;
        const float* bp = W + (size_t)(k0 + bk) * N + n0 + bn;
        *(float4*)&Bs[bk][bn]     = *(const float4*)bp;
        *(float4*)&Bs[bk][bn + 4] = *(const float4*)(bp + 4);
        __syncthreads();
        #pragma unroll
        for (int k = 0; k < 16; k++) {
            float4 a0v = *(const float4*)&As[k][ty * 8];
            float4 a1v = *(const float4*)&As[k][ty * 8 + 4];
            float4 b0v = *(const float4*)&Bs[k][tx * 8];
            float4 b1v = *(const float4*)&Bs[k][tx * 8 + 4];
            float a_[8] = {a0v.x, a0v.y, a0v.z, a0v.w, a1v.x, a1v.y, a1v.z, a1v.w};
            float b_[8] = {b0v.x, b0v.y, b0v.z, b0v.w, b1v.x, b1v.y, b1v.z, b1v.w};
            #pragma unroll
            for (int ii = 0; ii < 8; ii++)
                #pragma unroll
                for (int jj = 0; jj < 8; jj++)
                    acc[ii][jj] = fmaf(a_[ii], b_[jj], acc[ii][jj]);
        }
        __syncthreads();
    }
    #pragma unroll
    for (int ii = 0; ii < 8; ii++) {
        int m = m0 + ty * 8 + ii;
        #pragma unroll
        for (int jj = 0; jj < 8; jj++) {
            int n = n0 + tx * 8 + jj;
            float v = acc[ii][jj] + bias[n];
            if (act == 1) v = fmaxf(v, 0.0f);
            if (resid) v += resid[(size_t)m * N + n];
            C[(size_t)m * N + n] = v;
        }
    }
}

// ---------------- attention scores: per (b,h) Q[1024,64] @ K^T -> scores ----------
__global__ void __launch_bounds__(256) scores_kernel()
{
    int bh = blockIdx.z;
    int b = bh >> 4, h = bh & 15;
    int m0 = blockIdx.y * 128, n0 = blockIdx.x * 128;
    const float* qb = g_q + (size_t)b * S_ * (G_ * HD_) + (h >> 1) * HD_;
    const float* kb = g_k + (size_t)b * S_ * D_ + h * HD_;
    __shared__ float As[16][128];
    __shared__ float Bs[16][128];
    int tid = threadIdx.x;
    int tx = tid & 15, ty = tid >> 4;
    int r = tid >> 1, kq = (tid & 1) * 8;
    float acc[8][8] = {};
    for (int k0 = 0; k0 < HD_; k0 += 16) {
        const float* ap = qb + (size_t)(m0 + r) * (G_ * HD_) + k0 + kq;
        float4 a0 = *(const float4*)ap;
        float4 a1 = *(const float4*)(ap + 4);
        As[kq + 0][r] = a0.x; As[kq + 1][r] = a0.y; As[kq + 2][r] = a0.z; As[kq + 3][r] = a0.w;
        As[kq + 4][r] = a1.x; As[kq + 5][r] = a1.y; As[kq + 6][r] = a1.z; As[kq + 7][r] = a1.w;
        const float* bp = kb + (size_t)(n0 + r) * D_ + k0 + kq;
        float4 b0 = *(const float4*)bp;
        float4 b1 = *(const float4*)(bp + 4);
        Bs[kq + 0][r] = b0.x; Bs[kq + 1][r] = b0.y; Bs[kq + 2][r] = b0.z; Bs[kq + 3][r] = b0.w;
        Bs[kq + 4][r] = b1.x; Bs[kq + 5][r] = b1.y; Bs[kq + 6][r] = b1.z; Bs[kq + 7][r] = b1.w;
        __syncthreads();
        #pragma unroll
        for (int k = 0; k < 16; k++) {
            float4 a0v = *(const float4*)&As[k][ty * 8];
            float4 a1v = *(const float4*)&As[k][ty * 8 + 4];
            float4 b0v = *(const float4*)&Bs[k][tx * 8];
            float4 b1v = *(const float4*)&Bs[k][tx * 8 + 4];
            float a_[8] = {a0v.x, a0v.y, a0v.z, a0v.w, a1v.x, a1v.y, a1v.z, a1v.w};
            float b_[8] = {b0v.x, b0v.y, b0v.z, b0v.w, b1v.x, b1v.y, b1v.z, b1v.w};
            #pragma unroll
            for (int ii = 0; ii < 8; ii++)
                #pragma unroll
                for (int jj = 0; jj < 8; jj++)
                    acc[ii][jj] = fmaf(a_[ii], b_[jj], acc[ii][jj]);
        }
        __syncthreads();
    }
    float* C = g_sc + ((size_t)bh * S_ + m0) * S_ + n0;
    #pragma unroll
    for (int ii = 0; ii < 8; ii++)
        #pragma unroll
        for (int jj = 0; jj < 8; jj++)
            C[(size_t)(ty * 8 + ii) * S_ + tx * 8 + jj] = acc[ii][jj] * 0.125f;
}

// ---------------- softmax over last dim (row of 1024), register-resident ---------
__global__ void __launch_bounds__(256) softmax_kernel()
{
    float* p = g_sc + (size_t)blockIdx.x * S_;
    int tid = threadIdx.x;
    float4 v = *(const float4*)(p + tid * 4);
    __shared__ float red[256];
    red[tid] = fmaxf(fmaxf(v.x, v.y), fmaxf(v.z, v.w));
    __syncthreads();
    for (int o = 128; o; o >>= 1) { if (tid < o) red[tid] = fmaxf(red[tid], red[tid + o]); __syncthreads(); }
    float mx = red[0];
    __syncthreads();
    v.x = __expf(v.x - mx); v.y = __expf(v.y - mx);
    v.z = __expf(v.z - mx); v.w = __expf(v.w - mx);
    red[tid] = v.x + v.y + v.z + v.w;
    __syncthreads();
    for (int o = 128; o; o >>= 1) { if (tid < o) red[tid] += red[tid + o]; __syncthreads(); }
    float inv = 1.0f / red[0];
    v.x *= inv; v.y *= inv; v.z *= inv; v.w *= inv;
    *(float4*)(p + tid * 4) = v;
}

// ---------------- attn @ V: per (b,h) P[1024,1024] @ V[1024,64] -> ao --------------
__global__ void __launch_bounds__(256) av_kernel()
{
    int bh = blockIdx.y;
    int b = bh >> 4, h = bh & 15;
    int m0 = blockIdx.x * 128;
    const float* P  = g_sc + (size_t)bh * S_ * S_;
    const float* vb = g_v + (size_t)b * S_ * D_ + h * HD_;
    __shared__ float As[16][128];
    __shared__ float Bs[16][64];
    int tid = threadIdx.x;
    int tx = tid & 15, ty = tid >> 4;         // cols tx*4 (64), rows ty*8 (128)
    int am = tid >> 1, ak = (tid & 1) * 8;
    int bkr = tid >> 4, bnn = (tid & 15) * 4;
    float acc[8][4] = {};
    for (int k0 = 0; k0 < S_; k0 += 16) {
        const float* ap = P + (size_t)(m0 + am) * S_ + k0 + ak;
        float4 a0 = *(const float4*)ap;
        float4 a1 = *(const float4*)(ap + 4);
        As[ak + 0][am] = a0.x; As[ak + 1][am] = a0.y; As[ak + 2][am] = a0.z; As[ak + 3][am] = a0.w;
        As[ak + 4][am] = a1.x; As[ak + 5][am] = a1.y; As[ak + 6][am] = a1.z; As[ak + 7][am] = a1.w;
        *(float4*)&Bs[bkr][bnn] = *(const float4*)(vb + (size_t)(k0 + bkr) * D_ + bnn);
        __syncthreads();
        #pragma unroll
        for (int k = 0; k < 16; k++) {
            float4 a0v = *(const float4*)&As[k][ty * 8];
            float4 a1v = *(const float4*)&As[k][ty * 8 + 4];
            float4 bv  = *(const float4*)&Bs[k][tx * 4];
            float a_[8] = {a0v.x, a0v.y, a0v.z, a0v.w, a1v.x, a1v.y, a1v.z, a1v.w};
            float b_[4] = {bv.x, bv.y, bv.z, bv.w};
            #pragma unroll
            for (int ii = 0; ii < 8; ii++)
                #pragma unroll
                for (int jj = 0; jj < 4; jj++)
                    acc[ii][jj] = fmaf(a_[ii], b_[jj], acc[ii][jj]);
        }
        __syncthreads();
    }
    float* C = g_ao + (size_t)(b * S_ + m0) * D_ + h * HD_;
    #pragma unroll
    for (int ii = 0; ii < 8; ii++)
        #pragma unroll
        for (int jj = 0; jj < 4; jj++)
            C[(size_t)(ty * 8 + ii) * D_ + tx * 4 + jj] = acc[ii][jj];
}

// ---------------- gate: logits (warp per token), softmax, top-2, renorm ----------
__global__ void __launch_bounds__(256) gate_top2_kernel(const float* __restrict__ GW2,
                                                        const float* __restrict__ GB2)
{
    int warp = threadIdx.x >> 5, lane = threadIdx.x & 31;
    int t = blockIdx.x * 8 + warp;
    const float* gr = g_gh + (size_t)t * GH_;
    float lg[8] = {};
    for (int i = lane; i < GH_; i += 32) {
        float hv = gr[i];
        const float* wr = GW2 + (size_t)i * E_;
        #pragma unroll
        for (int e = 0; e < 8; e++) lg[e] = fmaf(hv, wr[e], lg[e]);
    }
    #pragma unroll
    for (int e = 0; e < 8; e++)
        for (int o = 16; o; o >>= 1) lg[e] += __shfl_xor_sync(0xffffffffu, lg[e], o);
    if (lane == 0) {
        float mx = -1e30f;
        #pragma unroll
        for (int e = 0; e < 8; e++) { lg[e] += GB2[e]; mx = fmaxf(mx, lg[e]); }
        float p[8], s = 0.0f;
        #pragma unroll
        for (int e = 0; e < 8; e++) { p[e] = __expf(lg[e] - mx); s += p[e]; }
        float invs = 1.0f / s;
        #pragma unroll
        for (int e = 0; e < 8; e++) p[e] *= invs;
        int i0 = 0;
        #pragma unroll
        for (int e = 1; e < 8; e++) if (p[e] > p[i0]) i0 = e;
        int i1 = -1;
        #pragma unroll
        for (int e = 0; e < 8; e++) {
            if (e == i0) continue;
            if (i1 < 0 || p[e] > p[i1]) i1 = e;
        }
        // renormalize: softmax over the two probability values (p[i0] >= p[i1])
        float z1 = __expf(p[i1] - p[i0]);
        float w0 = 1.0f / (1.0f + z1);
        float w1 = z1 / (1.0f + z1);
        g_topi[2 * t] = i0; g_topi[2 * t + 1] = i1;
        g_topw[2 * t] = w0; g_topw[2 * t + 1] = w1;
    }
}

// ---------------- routing ----------------
__global__ void count_kernel()
{
    int t = blockIdx.x * 256 + threadIdx.x;
    if (t < T_) {
        atomicAdd(&g_cnt[g_topi[2 * t]], 1);
        atomicAdd(&g_cnt[g_topi[2 * t + 1]], 1);
    }
}
__global__ void scan_kernel()
{
    if (threadIdx.x == 0) {
        int s = 0;
        for (int e = 0; e < E_; e++) { g_off[e] = s; s += g_cnt[e]; }
    }
}
__global__ void scatter_kernel()
{
    int t = blockIdx.x * 256 + threadIdx.x;
    if (t < T_) {
        #pragma unroll
        for (int k = 0; k < 2; k++) {
            int e = g_topi[2 * t + k];
            int pos = g_off[e] + atomicAdd(&g_cur[e], 1);
            g_pairs[pos] = t;
            g_pos[2 * t + k] = pos;
        }
    }
}

// ---------------- expert FFN1: gathered rows, gelu epilogue ----------------------
__global__ void __launch_bounds__(256) ffn1_kernel(const float* __restrict__ EW1,
                                                   const float* __restrict__ EB1)
{
    int e = blockIdx.z;
    int cnt = g_cnt[e];
    int m0 = blockIdx.y * 128;
    if (m0 >= cnt) return;
    int off = g_off[e];
    int n0 = blockIdx.x * 128;
    __shared__ float As[16][128];
    __shared__ float Bs[16][128];
    __shared__ int rowtok[128];
    int tid = threadIdx.x;
    if (tid < 128) {
        int mm = m0 + tid;
        rowtok[tid] = g_pairs[off + ((mm < cnt) ? mm : (cnt - 1))];
    }
    __syncthreads();
    int tx = tid & 15, ty = tid >> 4;
    int am = tid >> 1, ak = (tid & 1) * 8;
    int bk = tid >> 4, bn = (tid & 15) * 8;
    const float* W = EW1 + (size_t)e * D_ * ED_;
    float acc[8][8] = {};
    int tok = rowtok[am];
    for (int k0 = 0; k0 < D_; k0 += 16) {
        const float* ap = g_h2 + (size_t)tok * D_ + k0 + ak;
        float4 a0 = *(const float4*)ap;
        float4 a1 = *(const float4*)(ap + 4);
        As[ak + 0][am] = a0.x; As[ak + 1][am] = a0.y; As[ak + 2][am] = a0.z; As[ak + 3][am] = a0.w;
        As[ak + 4][am] = a1.x; As[ak + 5][am] = a1.y; As[ak + 6][am] = a1.z; As[ak + 7][am] = a1.w;
        const float* bp = W + (size_t)(k0 + bk) * ED_ + n0 + bn;
        *(float4*)&Bs[bk][bn]     = *(const float4*)bp;
        *(float4*)&Bs[bk][bn + 4] = *(const float4*)(bp + 4);
        __syncthreads();
        #pragma unroll
        for (int k = 0; k < 16; k++) {
            float4 a0v = *(const float4*)&As[k][ty * 8];
            float4 a1v = *(const float4*)&As[k][ty * 8 + 4];
            float4 b0v = *(const float4*)&Bs[k][tx * 8];
            float4 b1v = *(const float4*)&Bs[k][tx * 8 + 4];
            float a_[8] = {a0v.x, a0v.y, a0v.z, a0v.w, a1v.x, a1v.y, a1v.z, a1v.w};
            float b_[8] = {b0v.x, b0v.y, b0v.z, b0v.w, b1v.x, b1v.y, b1v.z, b1v.w};
            #pragma unroll
            for (int ii = 0; ii < 8; ii++)
                #pragma unroll
                for (int jj = 0; jj < 8; jj++)
                    acc[ii][jj] = fmaf(a_[ii], b_[jj], acc[ii][jj]);
        }
        __syncthreads();
    }
    #pragma unroll
    for (int ii = 0; ii < 8; ii++) {
        int m = m0 + ty * 8 + ii;
        if (m < cnt) {
            float* crow = g_hid + (size_t)(off + m) * ED_;
            #pragma unroll
            for (int jj = 0; jj < 8; jj++) {
                int n = n0 + tx * 8 + jj;
                float v = acc[ii][jj] + EB1[e * ED_ + n];
                v = 0.5f * v * (1.0f + erff(v * 0.70710678118654752f));
                crow[n] = v;
            }
        }
    }
}

// ---------------- expert FFN2: contiguous pair rows, bias epilogue ---------------
__global__ void __launch_bounds__(256) ffn2_kernel(const float* __restrict__ EW2,
                                                   const float* __restrict__ EB2)
{
    int e = blockIdx.z;
    int cnt = g_cnt[e];
    int m0 = blockIdx.y * 128;
    if (m0 >= cnt) return;
    int off = g_off[e];
    int n0 = blockIdx.x * 128;
    __shared__ float As[16][128];
    __shared__ float Bs[16][128];
    int tid = threadIdx.x;
    int tx = tid & 15, ty = tid >> 4;
    int am = tid >> 1, ak = (tid & 1) * 8;
    int bk = tid >> 4, bn = (tid & 15) * 8;
    const float* W = EW2 + (size_t)e * ED_ * D_;
    int ar = m0 + am; if (ar >= cnt) ar = cnt - 1;
    const float* arow = g_hid + (size_t)(off + ar) * ED_;
    float acc[8][8] = {};
    for (int k0 = 0; k0 < ED_; k0 += 16) {
        const float* ap = arow + k0 + ak;
        float4 a0 = *(const float4*)ap;
        float4 a1 = *(const float4*)(ap + 4);
        As[ak + 0][am] = a0.x; As[ak + 1][am] = a0.y; As[ak + 2][am] = a0.z; As[ak + 3][am] = a0.w;
        As[ak + 4][am] = a1.x; As[ak + 5][am] = a1.y; As[ak + 6][am] = a1.z; As[ak + 7][am] = a1.w;
        const float* bp = W + (size_t)(k0 + bk) * D_ + n0 + bn;
        *(float4*)&Bs[bk][bn]     = *(const float4*)bp;
        *(float4*)&Bs[bk][bn + 4] = *(const float4*)(bp + 4);
        __syncthreads();
        #pragma unroll
        for (int k = 0; k < 16; k++) {
            float4 a0v = *(const float4*)&As[k][ty * 8];
            float4 a1v = *(const float4*)&As[k][ty * 8 + 4];
            float4 b0v = *(const float4*)&Bs[k][tx * 8];
            float4 b1v = *(const float4*)&Bs[k][tx * 8 + 4];
            float a_[8] = {a0v.x, a0v.y, a0v.z, a0v.w, a1v.x, a1v.y, a1v.z, a1v.w};
            float b_[8] = {b0v.x, b0v.y, b0v.z, b0v.w, b1v.x, b1v.y, b1v.z, b1v.w};
            #pragma unroll
            for (int ii = 0; ii < 8; ii++)
                #pragma unroll
                for (int jj = 0; jj < 8; jj++)
                    acc[ii][jj] = fmaf(a_[ii], b_[jj], acc[ii][jj]);
        }
        __syncthreads();
    }
    #pragma unroll
    for (int ii = 0; ii < 8; ii++) {
        int m = m0 + ty * 8 + ii;
        if (m < cnt) {
            float* crow = g_eout + (size_t)(off + m) * D_;
            #pragma unroll
            for (int jj = 0; jj < 8; jj++) {
                int n = n0 + tx * 8 + jj;
                crow[n] = acc[ii][jj] + EB2[e * D_ + n];
            }
        }
    }
}

// ---------------- final combine: out = x1 + w0*eout[p0] + w1*eout[p1] -------------
__global__ void __launch_bounds__(256) combine_kernel(float* __restrict__ out)
{
    int t = blockIdx.x, tid = threadIdx.x;
    float w0 = g_topw[2 * t], w1 = g_topw[2 * t + 1];
    int p0 = g_pos[2 * t], p1 = g_pos[2 * t + 1];
    int i = tid * 4;
    float4 xv = *(const float4*)(g_x1 + (size_t)t * D_ + i);
    float4 a  = *(const float4*)(g_eout + (size_t)p0 * D_ + i);
    float4 b  = *(const float4*)(g_eout + (size_t)p1 * D_ + i);
    float4 o;
    o.x = xv.x + w0 * a.x + w1 * b.x;
    o.y = xv.y + w0 * a.y + w1 * b.y;
    o.z = xv.z + w0 * a.z + w1 * b.z;
    o.w = xv.w + w0 * a.w + w1 * b.w;
    *(float4*)(out + (size_t)t * D_ + i) = o;
}

// ---------------- host launch ----------------
extern "C" void kernel_launch(void* const* d_in, const int* in_sizes, int n_in,
                              void* d_out, int out_size)
{
    (void)in_sizes; (void)n_in; (void)out_size;
    const float* x    = (const float*)d_in[0];
    const float* wq   = (const float*)d_in[1];
    const float* bq   = (const float*)d_in[2];
    const float* wk   = (const float*)d_in[3];
    const float* bk   = (const float*)d_in[4];
    const float* wv   = (const float*)d_in[5];
    const float* bv   = (const float*)d_in[6];
    const float* wo   = (const float*)d_in[7];
    const float* bo   = (const float*)d_in[8];
    const float* ln1g = (const float*)d_in[9];
    const float* ln1b = (const float*)d_in[10];
    const float* ln2g = (const float*)d_in[11];
    const float* ln2b = (const float*)d_in[12];
    const float* gw1  = (const float*)d_in[13];
    const float* gb1  = (const float*)d_in[14];
    const float* gw2  = (const float*)d_in[15];
    const float* gb2  = (const float*)d_in[16];
    const float* ew1  = (const float*)d_in[17];
    const float* eb1  = (const float*)d_in[18];
    const float* ew2  = (const float*)d_in[19];
    const float* eb2  = (const float*)d_in[20];
    float* out = (float*)d_out;

    zero_kernel<<<1, 32>>>();
    // ln1: x -> g_h
    ln_kernel<<<T_, 256>>>(x, 0, ln1g, ln1b, 0);
    // q,k,v projections
    sgemm_kernel<<<dim3(4, 32), 256>>>(wq, bq, nullptr, 512,  1024, 0, 0, 0);  // g_h -> g_q
    sgemm_kernel<<<dim3(8, 32), 256>>>(wk, bk, nullptr, 1024, 1024, 0, 0, 1);  // g_h -> g_k
    sgemm_kernel<<<dim3(8, 32), 256>>>(wv, bv, nullptr, 1024, 1024, 0, 0, 2);  // g_h -> g_v
    // attention
    scores_kernel<<<dim3(8, 8, B_ * H_), 256>>>();
    softmax_kernel<<<B_ * H_ * S_, 256>>>();
    av_kernel<<<dim3(8, B_ * H_), 256>>>();
    // output projection + residual -> g_x1
    sgemm_kernel<<<dim3(8, 32), 256>>>(wo, bo, x, 1024, 1024, 0, 1, 3);        // g_ao -> g_x1
    // ln2: g_x1 -> g_h2
    ln_kernel<<<T_, 256>>>(x, 1, ln2g, ln2b, 1);
    // gate hidden (relu) -> g_gh
    sgemm_kernel<<<dim3(4, 32), 256>>>(gw1, gb1, nullptr, 512, 1024, 1, 2, 4); // g_h2 -> g_gh
    // gate logits + softmax + top2
    gate_top2_kernel<<<T_ / 8, 256>>>(gw2, gb2);
    // routing
    count_kernel<<<T_ / 256, 256>>>();
    scan_kernel<<<1, 32>>>();
    scatter_kernel<<<T_ / 256, 256>>>();
    // experts (top-2 sparse grouped GEMMs)
    ffn1_kernel<<<dim3(ED_ / 128, T_ / 128, E_), 256>>>(ew1, eb1);
    ffn2_kernel<<<dim3(D_ / 128, T_ / 128, E_), 256>>>(ew2, eb2);
    // combine
    combine_kernel<<<T_, 256>>>(out);
}